// round 11
// baseline (speedup 1.0000x reference)
#include <cuda_runtime.h>
#include <math.h>

#define BB 64
#define SS 4096
#define DD 256
#define WARPS 8
#define CPB 4                      // CTAs per batch
#define GROUPS 4                   // 8-lane groups per warp
#define RPG (SS/(CPB*WARPS*GROUPS))// 32 rows per group
#define LN_EPS 1e-3f

// Scratch (no cudaMalloc allowed)
__device__ float g_part_l[BB * CPB];                    // 1 KB
__device__ float g_part_acc[(size_t)BB * CPB * DD];     // 256 KB (L2-resident)
__device__ int   g_ticket[BB];                          // zero-init; self-resetting

// ---------------------------------------------------------------------------
// Fused single kernel: each CTA computes one additive partial (direct-exp
// softmax, scores bounded so no online max), publishes it, and the LAST CTA
// of each batch (atomic ticket) combines the 4 partials and writes out.
// Ticket self-resets to 0 so the kernel is graph-replay deterministic.
// ---------------------------------------------------------------------------
__global__ void __launch_bounds__(256, 2)
fused_kernel(const float* __restrict__ x,
             const float* __restrict__ mask,
             const float* __restrict__ gamma,
             const float* __restrict__ beta,
             const float* __restrict__ w,
             const float* __restrict__ bias,
             float* __restrict__ out)
{
    const int cta   = blockIdx.x;
    const int batch = cta / CPB;
    const int chunk = cta % CPB;
    const int wid   = threadIdx.x >> 5;
    const int lane  = threadIdx.x & 31;
    const int g     = lane >> 3;           // group within warp
    const int p     = lane & 7;            // lane within group

    __shared__ float swacc[WARPS][DD];     // 8 KB
    __shared__ float swl[WARPS];
    __shared__ int   s_last;

    // Per-lane LN/Dense constants over the 32 owned columns
    float gw[32];
    float gws = 0.0f, bw = 0.0f;
    #pragma unroll
    for (int j = 0; j < 8; j++) {
        float4 ga = ((const float4*)gamma)[p + 8*j];
        float4 ww = ((const float4*)w)[p + 8*j];
        float4 be = ((const float4*)beta)[p + 8*j];
        gw[4*j+0] = ga.x * ww.x;  gw[4*j+1] = ga.y * ww.y;
        gw[4*j+2] = ga.z * ww.z;  gw[4*j+3] = ga.w * ww.w;
        gws += gw[4*j+0] + gw[4*j+1] + gw[4*j+2] + gw[4*j+3];
        bw  += be.x*ww.x + be.y*ww.y + be.z*ww.z + be.w*ww.w;
    }
    #pragma unroll
    for (int off = 4; off > 0; off >>= 1) {
        gws += __shfl_xor_sync(0xffffffffu, gws, off);
        bw  += __shfl_xor_sync(0xffffffffu, bw,  off);
    }
    bw += bias[0];

    // This group's row range
    const int row0 = chunk * (SS / CPB) + wid * (SS / CPB / WARPS) + g * RPG;

    const float* xbase = x + ((size_t)batch * SS + row0) * DD;
    const float* mbase = mask + (size_t)batch * SS + row0;
    const float inv_d  = 1.0f / (float)DD;

    float l = 0.0f;
    float acc[32];
    #pragma unroll
    for (int i = 0; i < 32; i++) acc[i] = 0.0f;

    for (int r = 0; r < RPG; r++) {
        const float4* xr = (const float4*)(xbase + (size_t)r * DD);
        float4 a[8];
        #pragma unroll
        for (int j = 0; j < 8; j++) a[j] = __ldcs(xr + p + 8*j);  // stream, evict-first
        float mk = __ldg(mbase + r);

        float s1 = 0.f, s2 = 0.f, sw = 0.f;
        #pragma unroll
        for (int j = 0; j < 8; j++) {
            s1 += a[j].x + a[j].y + a[j].z + a[j].w;
            s2 = fmaf(a[j].x, a[j].x, s2); s2 = fmaf(a[j].y, a[j].y, s2);
            s2 = fmaf(a[j].z, a[j].z, s2); s2 = fmaf(a[j].w, a[j].w, s2);
            sw = fmaf(a[j].x, gw[4*j+0], sw); sw = fmaf(a[j].y, gw[4*j+1], sw);
            sw = fmaf(a[j].z, gw[4*j+2], sw); sw = fmaf(a[j].w, gw[4*j+3], sw);
        }
        #pragma unroll
        for (int off = 4; off > 0; off >>= 1) {
            s1 += __shfl_xor_sync(0xffffffffu, s1, off);
            s2 += __shfl_xor_sync(0xffffffffu, s2, off);
            sw += __shfl_xor_sync(0xffffffffu, sw, off);
        }

        float mu    = s1 * inv_d;
        float var   = fmaf(-mu, mu, s2 * inv_d);
        float rstd  = rsqrtf(var + LN_EPS);
        float score = fmaf(rstd, sw - mu * gws, bw);
        score = fmaf(1.0f - mk, -1e9f, score);

        // Direct exp (scores bounded; masked rows give exp(-1e9)=0)
        float e = __expf(score);
        l += e;
        #pragma unroll
        for (int j = 0; j < 8; j++) {
            acc[4*j+0] = fmaf(e, a[j].x, acc[4*j+0]);
            acc[4*j+1] = fmaf(e, a[j].y, acc[4*j+1]);
            acc[4*j+2] = fmaf(e, a[j].z, acc[4*j+2]);
            acc[4*j+3] = fmaf(e, a[j].w, acc[4*j+3]);
        }
    }

    // ---- Epilogue: additive combine of the CTA's 32 groups ----
    #pragma unroll
    for (int i = 0; i < 32; i++) {
        acc[i] += __shfl_xor_sync(0xffffffffu, acc[i], 8);
        acc[i] += __shfl_xor_sync(0xffffffffu, acc[i], 16);
    }
    l += __shfl_xor_sync(0xffffffffu, l, 8);
    l += __shfl_xor_sync(0xffffffffu, l, 16);

    if (lane < 8) {
        float4* drow = (float4*)swacc[wid];
        #pragma unroll
        for (int j = 0; j < 8; j++)
            drow[p + 8*j] = make_float4(acc[4*j+0], acc[4*j+1], acc[4*j+2], acc[4*j+3]);
        if (lane == 0) swl[wid] = l;
    }
    __syncthreads();

    const int t = threadIdx.x;
    float v = swacc[0][t];
    #pragma unroll
    for (int k = 1; k < WARPS; k++) v += swacc[k][t];
    g_part_acc[(size_t)cta * DD + t] = v;

    if (t == 0) {
        float lc = swl[0];
        #pragma unroll
        for (int k = 1; k < WARPS; k++) lc += swl[k];
        g_part_l[cta] = lc;
    }
    __syncthreads();

    // ---- Ticket: last CTA of this batch combines the partials ----
    if (t == 0) {
        __threadfence();                       // publish partials
        int old = atomicAdd(&g_ticket[batch], 1);
        s_last = (old == CPB - 1) ? 1 : 0;
    }
    __syncthreads();

    if (s_last) {
        __threadfence();                       // acquire peers' partials
        const float* accb = g_part_acc + (size_t)batch * CPB * DD;
        float s = 0.0f;
        #pragma unroll
        for (int i = 0; i < CPB; i++) s += accb[(size_t)i * DD + t];

        float L = 0.0f;
        #pragma unroll
        for (int i = 0; i < CPB; i++) L += g_part_l[batch * CPB + i];

        out[batch * DD + t] = s / L;
        if (t == 0) g_ticket[batch] = 0;       // reset for next graph replay
    }
}

// ---------------------------------------------------------------------------
extern "C" void kernel_launch(void* const* d_in, const int* in_sizes, int n_in,
                              void* d_out, int out_size)
{
    const float* x     = (const float*)d_in[0];
    const float* mask  = (const float*)d_in[1];
    const float* gamma = (const float*)d_in[2];
    const float* beta  = (const float*)d_in[3];
    const float* w     = (const float*)d_in[4];
    const float* bias  = (const float*)d_in[5];
    float* out = (float*)d_out;

    fused_kernel<<<BB * CPB, 256>>>(x, mask, gamma, beta, w, bias, out);
}